// round 1
// baseline (speedup 1.0000x reference)
#include <cuda_runtime.h>
#include <cuda_bf16.h>

// Problem constants (validated against in_sizes at launch).
#define EMB 256
#define MAX_NODES 100000
#define MAX_EDGES 3200000

// -------- device scratch (no allocations allowed) --------
__device__ float d_P[MAX_NODES * EMB];   // P = embeddings @ W  (102.4 MB)
__device__ int   d_rowptr[MAX_NODES + 1];
__device__ int   d_cursor[MAX_NODES + 1]; // counts, then scatter cursors
__device__ int   d_scol[MAX_EDGES];
__device__ float d_sval[MAX_EDGES];

// ---------------- K0: zero counts ----------------
__global__ void zero_counts_kernel(int n) {
    int i = blockIdx.x * blockDim.x + threadIdx.x;
    if (i <= n) d_cursor[i] = 0;
}

// ---------------- K1: histogram of rows ----------------
__global__ void hist_kernel(const int* __restrict__ rows, int E) {
    int e = blockIdx.x * blockDim.x + threadIdx.x;
    if (e < E) atomicAdd(&d_cursor[rows[e]], 1);
}

// ---------------- K2: single-block exclusive scan ----------------
// counts live in d_cursor[0..n-1]; writes rowptr[0..n] and resets cursor=rowptr.
__global__ void scan_kernel(int n) {
    __shared__ int s[1024];
    __shared__ int carry_s;
    const int t = threadIdx.x;
    if (t == 0) carry_s = 0;
    __syncthreads();
    for (int base = 0; base < n; base += 1024) {
        int i = base + t;
        int v = (i < n) ? d_cursor[i] : 0;
        s[t] = v;
        __syncthreads();
        // Kogge-Stone inclusive scan
        #pragma unroll
        for (int off = 1; off < 1024; off <<= 1) {
            int x = (t >= off) ? s[t - off] : 0;
            __syncthreads();
            s[t] += x;
            __syncthreads();
        }
        int incl = s[t];
        int carry = carry_s;
        if (i < n) {
            int excl = carry + incl - v;
            d_rowptr[i] = excl;
            d_cursor[i] = excl;   // scatter cursor
        }
        __syncthreads();
        if (t == 1023) carry_s = carry + s[1023];
        __syncthreads();
    }
    if (t == 0) d_rowptr[n] = carry_s;
}

// ---------------- K3: scatter edges into CSR order ----------------
__global__ void scatter_kernel(const int* __restrict__ rows,
                               const int* __restrict__ cols,
                               const float* __restrict__ vals, int E) {
    int e = blockIdx.x * blockDim.x + threadIdx.x;
    if (e < E) {
        int r = rows[e];
        int p = atomicAdd(&d_cursor[r], 1);
        d_scol[p] = cols[e];
        d_sval[p] = vals[e];
    }
}

// ---------------- K4: P = embeddings @ W  (fp32 tiled SGEMM) ----------------
// M x 256 @ 256 x 256. BM=64, BN=64, BK=32, 256 threads, 4x4 per thread.
#define BM 64
#define BN 64
#define BK 32
__global__ __launch_bounds__(256) void gemm_kernel(const float* __restrict__ A,
                                                   const float* __restrict__ B,
                                                   int M) {
    __shared__ float sA[BK][BM + 1];
    __shared__ float sB[BK][BN];
    const int tid = threadIdx.x;
    const int tx = tid & 15;        // 0..15 -> N
    const int ty = tid >> 4;        // 0..15 -> M
    const int row0 = blockIdx.x * BM;
    const int col0 = blockIdx.y * BN;

    float acc[4][4];
    #pragma unroll
    for (int m = 0; m < 4; m++)
        #pragma unroll
        for (int n = 0; n < 4; n++) acc[m][n] = 0.f;

    for (int k0 = 0; k0 < EMB; k0 += BK) {
        // A tile: BM x BK, coalesced along K; store transposed sA[k][m]
        #pragma unroll
        for (int i = tid; i < BM * BK; i += 256) {
            int r = i >> 5;          // /BK
            int c = i & 31;          // %BK
            float a = (row0 + r < M) ? A[(long)(row0 + r) * EMB + k0 + c] : 0.f;
            sA[c][r] = a;
        }
        // B tile: BK x BN
        #pragma unroll
        for (int i = tid; i < BK * BN; i += 256) {
            int r = i >> 6;          // /BN
            int c = i & 63;          // %BN
            sB[r][c] = B[(k0 + r) * EMB + col0 + c];
        }
        __syncthreads();
        #pragma unroll
        for (int k = 0; k < BK; k++) {
            float a[4];
            #pragma unroll
            for (int m = 0; m < 4; m++) a[m] = sA[k][ty * 4 + m];
            float4 b4 = *reinterpret_cast<const float4*>(&sB[k][tx * 4]);
            float b[4] = {b4.x, b4.y, b4.z, b4.w};
            #pragma unroll
            for (int m = 0; m < 4; m++)
                #pragma unroll
                for (int n = 0; n < 4; n++)
                    acc[m][n] = fmaf(a[m], b[n], acc[m][n]);
        }
        __syncthreads();
    }
    #pragma unroll
    for (int m = 0; m < 4; m++) {
        int r = row0 + ty * 4 + m;
        if (r < M) {
            float4 o = {acc[m][0], acc[m][1], acc[m][2], acc[m][3]};
            *reinterpret_cast<float4*>(&d_P[(long)r * EMB + col0 + tx * 4]) = o;
        }
    }
}

// ---------------- K5: SpMM in P-space + ReLU -> out ----------------
// One warp per output row. Each lane owns 8 floats (2 float4) of the 256-wide row.
__global__ __launch_bounds__(256) void spmm_relu_kernel(float* __restrict__ out,
                                                        int nrows) {
    const int warp = blockIdx.x * (blockDim.x >> 5) + (threadIdx.x >> 5);
    if (warp >= nrows) return;
    const int lane = threadIdx.x & 31;
    const int s = d_rowptr[warp];
    const int e = d_rowptr[warp + 1];

    float4 acc0 = {0.f, 0.f, 0.f, 0.f};
    float4 acc1 = {0.f, 0.f, 0.f, 0.f};
    const float4* __restrict__ Pv = reinterpret_cast<const float4*>(d_P);

    for (int base = s; base < e; base += 32) {
        int idx = base + lane;
        int c = 0;
        float v = 0.f;
        if (idx < e) { c = d_scol[idx]; v = d_sval[idx]; }
        int cnt = e - base; if (cnt > 32) cnt = 32;
        #pragma unroll 4
        for (int j = 0; j < cnt; j++) {
            int   cj = __shfl_sync(0xffffffffu, c, j);
            float vj = __shfl_sync(0xffffffffu, v, j);
            float4 p0 = Pv[(long)cj * 64 + lane];
            float4 p1 = Pv[(long)cj * 64 + 32 + lane];
            acc0.x = fmaf(vj, p0.x, acc0.x);
            acc0.y = fmaf(vj, p0.y, acc0.y);
            acc0.z = fmaf(vj, p0.z, acc0.z);
            acc0.w = fmaf(vj, p0.w, acc0.w);
            acc1.x = fmaf(vj, p1.x, acc1.x);
            acc1.y = fmaf(vj, p1.y, acc1.y);
            acc1.z = fmaf(vj, p1.z, acc1.z);
            acc1.w = fmaf(vj, p1.w, acc1.w);
        }
    }
    acc0.x = fmaxf(acc0.x, 0.f); acc0.y = fmaxf(acc0.y, 0.f);
    acc0.z = fmaxf(acc0.z, 0.f); acc0.w = fmaxf(acc0.w, 0.f);
    acc1.x = fmaxf(acc1.x, 0.f); acc1.y = fmaxf(acc1.y, 0.f);
    acc1.z = fmaxf(acc1.z, 0.f); acc1.w = fmaxf(acc1.w, 0.f);
    float4* outv = reinterpret_cast<float4*>(out);
    outv[(long)warp * 64 + lane]      = acc0;
    outv[(long)warp * 64 + 32 + lane] = acc1;
}

// ---------------- launch ----------------
extern "C" void kernel_launch(void* const* d_in, const int* in_sizes, int n_in,
                              void* d_out, int out_size) {
    const float* emb  = (const float*)d_in[0];
    const int*   rows = (const int*)  d_in[1];
    const int*   cols = (const int*)  d_in[2];
    const float* vals = (const float*)d_in[3];
    const float* W    = (const float*)d_in[4];
    float* out = (float*)d_out;

    const int N = in_sizes[0] / EMB;   // 100000
    const int E = in_sizes[1];         // 3200000

    // Dense projection in parallel with CSR build (same stream, but GEMM
    // is independent of edge data ordering).
    dim3 ggrid((N + BM - 1) / BM, EMB / BN);
    gemm_kernel<<<ggrid, 256>>>(emb, W, N);

    // CSR build
    zero_counts_kernel<<<(N + 256) / 256, 256>>>(N);
    hist_kernel<<<(E + 255) / 256, 256>>>(rows, E);
    scan_kernel<<<1, 1024>>>(N);
    scatter_kernel<<<(E + 255) / 256, 256>>>(rows, cols, vals, E);

    // Row-parallel aggregate in P-space + ReLU -> final output
    int warps_per_block = 256 / 32;
    int sgrid = (N + warps_per_block - 1) / warps_per_block;
    spmm_relu_kernel<<<sgrid, 256>>>(out, N);
}

// round 2
// speedup vs baseline: 1.6765x; 1.6765x over previous
#include <cuda_runtime.h>
#include <cuda_bf16.h>

// Problem constants.
#define EMB 256
#define MAX_NODES 100000
#define MAX_EDGES 3200000
#define SCAN_BLK 1024
#define MAX_SCAN_BLOCKS 128   // ceil(100001/1024) = 98

// -------- device scratch (no allocations allowed) --------
__device__ float d_P[MAX_NODES * EMB];   // P = embeddings @ W  (102.4 MB)
__device__ int   d_rowptr[MAX_NODES + 1];
__device__ int   d_cursor[MAX_NODES + 1]; // counts, then scatter cursors
__device__ int   d_scol[MAX_EDGES];
__device__ float d_sval[MAX_EDGES];
__device__ int   d_blocksums[MAX_SCAN_BLOCKS];
__device__ int   d_blockoffs[MAX_SCAN_BLOCKS];

// ---------------- K0: zero counts ----------------
__global__ void zero_counts_kernel(int n) {
    int i = blockIdx.x * blockDim.x + threadIdx.x;
    if (i <= n) d_cursor[i] = 0;
}

// ---------------- K1: histogram of rows ----------------
__global__ void hist_kernel(const int* __restrict__ rows, int E) {
    int e = blockIdx.x * blockDim.x + threadIdx.x;
    if (e < E) atomicAdd(&d_cursor[rows[e]], 1);
}

// ---------------- scan helpers ----------------
__device__ __forceinline__ int warp_incl_scan(int v, int lane) {
    #pragma unroll
    for (int off = 1; off < 32; off <<= 1) {
        int x = __shfl_up_sync(0xffffffffu, v, off);
        if (lane >= off) v += x;
    }
    return v;
}

// K2a: per-block inclusive scan of counts; write local-exclusive to rowptr,
// block total to d_blocksums.
__global__ __launch_bounds__(SCAN_BLK) void scan_block_kernel(int n) {
    __shared__ int wsum[SCAN_BLK / 32];
    const int t = threadIdx.x;
    const int lane = t & 31;
    const int warp = t >> 5;
    const int i = blockIdx.x * SCAN_BLK + t;

    int v = (i < n) ? d_cursor[i] : 0;
    int incl = warp_incl_scan(v, lane);
    if (lane == 31) wsum[warp] = incl;
    __syncthreads();
    if (warp == 0) {
        int s = (lane < SCAN_BLK / 32) ? wsum[lane] : 0;
        s = warp_incl_scan(s, lane);
        if (lane < SCAN_BLK / 32) wsum[lane] = s;
    }
    __syncthreads();
    int base = (warp > 0) ? wsum[warp - 1] : 0;
    if (i < n) d_rowptr[i] = base + incl - v;   // local exclusive
    if (t == SCAN_BLK - 1) d_blocksums[blockIdx.x] = base + incl;
}

// K2b: scan the block sums (<=128) in one block; write exclusive offsets
// and the grand total to d_rowptr[n].
__global__ __launch_bounds__(128) void scan_sums_kernel(int nblocks, int n) {
    __shared__ int wsum[4];
    const int t = threadIdx.x;
    const int lane = t & 31;
    const int warp = t >> 5;
    int v = (t < nblocks) ? d_blocksums[t] : 0;
    int incl = warp_incl_scan(v, lane);
    if (lane == 31) wsum[warp] = incl;
    __syncthreads();
    if (warp == 0) {
        int s = (lane < 4) ? wsum[lane] : 0;
        s = warp_incl_scan(s, lane);
        if (lane < 4) wsum[lane] = s;
    }
    __syncthreads();
    int base = (warp > 0) ? wsum[warp - 1] : 0;
    if (t < nblocks) d_blockoffs[t] = base + incl - v;  // exclusive
    if (t == 127) d_rowptr[n] = wsum[3];                // grand total
}

// K2c: add block offsets; also seed scatter cursors.
__global__ __launch_bounds__(SCAN_BLK) void scan_add_kernel(int n) {
    const int i = blockIdx.x * SCAN_BLK + threadIdx.x;
    if (i < n) {
        int r = d_rowptr[i] + d_blockoffs[blockIdx.x];
        d_rowptr[i] = r;
        d_cursor[i] = r;
    }
}

// ---------------- K3: scatter edges into CSR order ----------------
__global__ void scatter_kernel(const int* __restrict__ rows,
                               const int* __restrict__ cols,
                               const float* __restrict__ vals, int E) {
    int e = blockIdx.x * blockDim.x + threadIdx.x;
    if (e < E) {
        int r = rows[e];
        int p = atomicAdd(&d_cursor[r], 1);
        d_scol[p] = cols[e];
        d_sval[p] = vals[e];
    }
}

// ---------------- K4: P = embeddings @ W  (fp32 tiled SGEMM) ----------------
#define BM 64
#define BN 64
#define BK 32
__global__ __launch_bounds__(256) void gemm_kernel(const float* __restrict__ A,
                                                   const float* __restrict__ B,
                                                   int M) {
    __shared__ float sA[BK][BM + 1];
    __shared__ float sB[BK][BN];
    const int tid = threadIdx.x;
    const int tx = tid & 15;        // 0..15 -> N
    const int ty = tid >> 4;        // 0..15 -> M
    const int row0 = blockIdx.x * BM;
    const int col0 = blockIdx.y * BN;

    float acc[4][4];
    #pragma unroll
    for (int m = 0; m < 4; m++)
        #pragma unroll
        for (int n = 0; n < 4; n++) acc[m][n] = 0.f;

    for (int k0 = 0; k0 < EMB; k0 += BK) {
        #pragma unroll
        for (int i = tid; i < BM * BK; i += 256) {
            int r = i >> 5;
            int c = i & 31;
            float a = (row0 + r < M) ? A[(long)(row0 + r) * EMB + k0 + c] : 0.f;
            sA[c][r] = a;
        }
        #pragma unroll
        for (int i = tid; i < BK * BN; i += 256) {
            int r = i >> 6;
            int c = i & 63;
            sB[r][c] = B[(k0 + r) * EMB + col0 + c];
        }
        __syncthreads();
        #pragma unroll
        for (int k = 0; k < BK; k++) {
            float a[4];
            #pragma unroll
            for (int m = 0; m < 4; m++) a[m] = sA[k][ty * 4 + m];
            float4 b4 = *reinterpret_cast<const float4*>(&sB[k][tx * 4]);
            float b[4] = {b4.x, b4.y, b4.z, b4.w};
            #pragma unroll
            for (int m = 0; m < 4; m++)
                #pragma unroll
                for (int n = 0; n < 4; n++)
                    acc[m][n] = fmaf(a[m], b[n], acc[m][n]);
        }
        __syncthreads();
    }
    #pragma unroll
    for (int m = 0; m < 4; m++) {
        int r = row0 + ty * 4 + m;
        if (r < M) {
            float4 o = {acc[m][0], acc[m][1], acc[m][2], acc[m][3]};
            *reinterpret_cast<float4*>(&d_P[(long)r * EMB + col0 + tx * 4]) = o;
        }
    }
}

// ---------------- K5: SpMM in P-space + ReLU -> out ----------------
__global__ __launch_bounds__(256) void spmm_relu_kernel(float* __restrict__ out,
                                                        int nrows) {
    const int warp = blockIdx.x * (blockDim.x >> 5) + (threadIdx.x >> 5);
    if (warp >= nrows) return;
    const int lane = threadIdx.x & 31;
    const int s = d_rowptr[warp];
    const int e = d_rowptr[warp + 1];

    float4 acc0 = {0.f, 0.f, 0.f, 0.f};
    float4 acc1 = {0.f, 0.f, 0.f, 0.f};
    const float4* __restrict__ Pv = reinterpret_cast<const float4*>(d_P);

    for (int base = s; base < e; base += 32) {
        int idx = base + lane;
        int c = 0;
        float v = 0.f;
        if (idx < e) { c = d_scol[idx]; v = d_sval[idx]; }
        int cnt = e - base; if (cnt > 32) cnt = 32;
        #pragma unroll 4
        for (int j = 0; j < cnt; j++) {
            int   cj = __shfl_sync(0xffffffffu, c, j);
            float vj = __shfl_sync(0xffffffffu, v, j);
            float4 p0 = Pv[(long)cj * 64 + lane];
            float4 p1 = Pv[(long)cj * 64 + 32 + lane];
            acc0.x = fmaf(vj, p0.x, acc0.x);
            acc0.y = fmaf(vj, p0.y, acc0.y);
            acc0.z = fmaf(vj, p0.z, acc0.z);
            acc0.w = fmaf(vj, p0.w, acc0.w);
            acc1.x = fmaf(vj, p1.x, acc1.x);
            acc1.y = fmaf(vj, p1.y, acc1.y);
            acc1.z = fmaf(vj, p1.z, acc1.z);
            acc1.w = fmaf(vj, p1.w, acc1.w);
        }
    }
    acc0.x = fmaxf(acc0.x, 0.f); acc0.y = fmaxf(acc0.y, 0.f);
    acc0.z = fmaxf(acc0.z, 0.f); acc0.w = fmaxf(acc0.w, 0.f);
    acc1.x = fmaxf(acc1.x, 0.f); acc1.y = fmaxf(acc1.y, 0.f);
    acc1.z = fmaxf(acc1.z, 0.f); acc1.w = fmaxf(acc1.w, 0.f);
    float4* outv = reinterpret_cast<float4*>(out);
    outv[(long)warp * 64 + lane]      = acc0;
    outv[(long)warp * 64 + 32 + lane] = acc1;
}

// ---------------- launch ----------------
extern "C" void kernel_launch(void* const* d_in, const int* in_sizes, int n_in,
                              void* d_out, int out_size) {
    const float* emb  = (const float*)d_in[0];
    const int*   rows = (const int*)  d_in[1];
    const int*   cols = (const int*)  d_in[2];
    const float* vals = (const float*)d_in[3];
    const float* W    = (const float*)d_in[4];
    float* out = (float*)d_out;

    const int N = in_sizes[0] / EMB;   // 100000
    const int E = in_sizes[1];         // 3200000

    // Dense projection (independent of CSR build).
    dim3 ggrid((N + BM - 1) / BM, EMB / BN);
    gemm_kernel<<<ggrid, 256>>>(emb, W, N);

    // CSR build with multi-level scan
    const int nsb = (N + SCAN_BLK - 1) / SCAN_BLK;   // 98
    zero_counts_kernel<<<(N + 256) / 256, 256>>>(N);
    hist_kernel<<<(E + 511) / 512, 512>>>(rows, E);
    scan_block_kernel<<<nsb, SCAN_BLK>>>(N);
    scan_sums_kernel<<<1, 128>>>(nsb, N);
    scan_add_kernel<<<nsb, SCAN_BLK>>>(N);
    scatter_kernel<<<(E + 511) / 512, 512>>>(rows, cols, vals, E);

    // Row-parallel aggregate in P-space + ReLU -> final output
    int warps_per_block = 256 / 32;
    int sgrid = (N + warps_per_block - 1) / warps_per_block;
    spmm_relu_kernel<<<sgrid, 256>>>(out, N);
}